// round 15
// baseline (speedup 1.0000x reference)
#include <cuda_runtime.h>
#include <cstdint>

#define N_NODES 250000
#define N_EDGES 4000000
#define NODE_F  4
#define HID     32
#define NN      50
#define NF      3
#define OUT_C   53
#define TILES   (N_EDGES / 32)
#define N_TAIL  ((N_NODES / NN) * NF)   // 15000

// Scratch (device globals)
__device__ float  g_accC[N_NODES];                 // 1 MB
__device__ __align__(8) float2 g_accMS[N_TAIL];    // 120 KB compact tail accumulators
__device__ float g_conc[N_NODES];
__device__ float g_S;
__device__ int   g_ei_is64;
__device__ float g_sc, g_sm, g_ss;                 // b2 . W*[4:36]
__device__ unsigned g_W1t[8 * HID];                // tf32 W1 rows 0..7
__device__ __align__(16) float4 g_epi0[16];        // {uc0, uc1, um0, um1} per col-pair
__device__ __align__(16) float4 g_epi1[16];        // {us0, us1, w8_0, w8_1}
__device__ __align__(8)  float2 g_epi2[16];        // {b0, b1}

__device__ __forceinline__ float softplusf(float x) {
    return fmaxf(x, 0.0f) + log1pf(expf(-fabsf(x)));
}
__device__ __forceinline__ unsigned f2tf32(float f) {
    unsigned u; asm("cvt.rna.tf32.f32 %0, %1;" : "=r"(u) : "f"(f)); return u;
}
__device__ __forceinline__ void mma_tf32(float d[4],
                                         unsigned a0, unsigned a1, unsigned a2, unsigned a3,
                                         unsigned b0, unsigned b1) {
    asm("mma.sync.aligned.m16n8k8.row.col.f32.tf32.tf32.f32 "
        "{%0,%1,%2,%3}, {%4,%5,%6,%7}, {%8,%9}, {%0,%1,%2,%3};"
        : "+f"(d[0]), "+f"(d[1]), "+f"(d[2]), "+f"(d[3])
        : "r"(a0), "r"(a1), "r"(a2), "r"(a3), "r"(b0), "r"(b1));
}

// ---------------------------------------------------------------------------
// Launch 1: prep
// ---------------------------------------------------------------------------
__global__ void prep_kernel(const int* __restrict__ ei32,
                            const float* __restrict__ W1,
                            const float* __restrict__ b1,
                            const float* __restrict__ W2,
                            const float* __restrict__ b2,
                            const float* __restrict__ Wc,
                            const float* __restrict__ Wmu,
                            const float* __restrict__ Wsig)
{
    __shared__ float suc[HID], sum_[HID], sus[HID];
    const int k = threadIdx.x;
    if (k == 0) {
        int z = 0;
        #pragma unroll
        for (int i = 1; i < 64; i += 2) z |= ei32[i];
        g_ei_is64 = (z == 0) ? 1 : 0;
        g_S = 0.0f;
    }
    float uc = 0.f, um = 0.f, us = 0.f;
    #pragma unroll
    for (int m = 0; m < HID; m++) {
        const float w = W2[k * HID + m];
        uc = fmaf(w, Wc[NODE_F + m],   uc);
        um = fmaf(w, Wmu[NODE_F + m],  um);
        us = fmaf(w, Wsig[NODE_F + m], us);
    }
    suc[k] = uc; sum_[k] = um; sus[k] = us;

    #pragma unroll
    for (int d = 0; d < 8; d++) g_W1t[d * HID + k] = f2tf32(W1[d * HID + k]);

    __syncwarp();
    if (k < 16) {
        const int c0 = 2 * k, c1 = 2 * k + 1;
        g_epi0[k] = make_float4(suc[c0], suc[c1], sum_[c0], sum_[c1]);
        g_epi1[k] = make_float4(sus[c0], sus[c1], W1[8 * HID + c0], W1[8 * HID + c1]);
        g_epi2[k] = make_float2(b1[c0], b1[c1]);
    }

    float pc = b2[k] * Wc[NODE_F + k];
    float pm = b2[k] * Wmu[NODE_F + k];
    float ps = b2[k] * Wsig[NODE_F + k];
    #pragma unroll
    for (int off = 16; off > 0; off >>= 1) {
        pc += __shfl_xor_sync(0xffffffffu, pc, off);
        pm += __shfl_xor_sync(0xffffffffu, pm, off);
        ps += __shfl_xor_sync(0xffffffffu, ps, off);
    }
    if (k == 0) { g_sc = pc; g_sm = pm; g_ss = ps; }
}

// ---------------------------------------------------------------------------
// Launch 2 / 3: zero accC, zero compact accMS
// ---------------------------------------------------------------------------
__global__ void zeroC_kernel() {
    const int i = blockIdx.x * blockDim.x + threadIdx.x;
    if (i < N_NODES) g_accC[i] = 0.0f;
}
__global__ void zeroMS_kernel() {
    const int i = blockIdx.x * blockDim.x + threadIdx.x;
    if (i < N_TAIL) g_accMS[i] = make_float2(0.f, 0.f);
}

// ---------------------------------------------------------------------------
// Per-half-tile worker
// ---------------------------------------------------------------------------
__device__ __forceinline__ void process_half(
    float f0, float f1, float f2, float f3,
    float eaA, float eaB, int rA, int rB,
    const unsigned B0[4], const unsigned B1[4],
    const float4* sE0, const float4* sE1, const float2* sE2,
    int tig, unsigned qmask, float sc, float sm, float ss)
{
    const unsigned a0 = f2tf32(f0), a1 = f2tf32(f1);
    const unsigned a2 = f2tf32(f2), a3 = f2tf32(f3);
    float D[4][4];
    #pragma unroll
    for (int nt = 0; nt < 4; nt++) {
        D[nt][0] = D[nt][1] = D[nt][2] = D[nt][3] = 0.0f;
        mma_tf32(D[nt], a0, a1, a2, a3, B0[nt], B1[nt]);
    }

    const int pA = rA % NN, pB = rB % NN;
    const bool needA = (pA >= NN - NF);
    const bool needB = (pB >= NN - NF);
    const bool needMS = needA || needB;          // quad-uniform

    float pcA = 0.f, pcB = 0.f, pmA = 0.f, pmB = 0.f, psA = 0.f, psB = 0.f;
    #pragma unroll
    for (int nt = 0; nt < 4; nt++) {
        const int p = nt * 4 + tig;
        const float4 E1 = sE1[p];   // us0, us1, w8_0, w8_1
        const float2 E2 = sE2[p];   // b0, b1
        const float h0 = fmaxf(fmaf(eaA, E1.z, D[nt][0] + E2.x), 0.f);
        const float h1 = fmaxf(fmaf(eaA, E1.w, D[nt][1] + E2.y), 0.f);
        const float h2 = fmaxf(fmaf(eaB, E1.z, D[nt][2] + E2.x), 0.f);
        const float h3 = fmaxf(fmaf(eaB, E1.w, D[nt][3] + E2.y), 0.f);
        const float4 E0 = sE0[p];   // uc0, uc1, um0, um1
        pcA = fmaf(h0, E0.x, fmaf(h1, E0.y, pcA));
        pcB = fmaf(h2, E0.x, fmaf(h3, E0.y, pcB));
        if (needMS) {
            pmA = fmaf(h0, E0.z, fmaf(h1, E0.w, pmA));
            pmB = fmaf(h2, E0.z, fmaf(h3, E0.w, pmB));
            psA = fmaf(h0, E1.x, fmaf(h1, E1.y, psA));
            psB = fmaf(h2, E1.x, fmaf(h3, E1.y, psB));
        }
    }

    pcA += __shfl_xor_sync(qmask, pcA, 1); pcA += __shfl_xor_sync(qmask, pcA, 2);
    pcB += __shfl_xor_sync(qmask, pcB, 1); pcB += __shfl_xor_sync(qmask, pcB, 2);
    if (needMS) {
        pmA += __shfl_xor_sync(qmask, pmA, 1); pmA += __shfl_xor_sync(qmask, pmA, 2);
        pmB += __shfl_xor_sync(qmask, pmB, 1); pmB += __shfl_xor_sync(qmask, pmB, 2);
        psA += __shfl_xor_sync(qmask, psA, 1); psA += __shfl_xor_sync(qmask, psA, 2);
        psB += __shfl_xor_sync(qmask, psB, 1); psB += __shfl_xor_sync(qmask, psB, 2);
    }

    if (tig == 0) {
        asm volatile("red.global.add.f32 [%0], %1;"
                     :: "l"(&g_accC[rA]), "f"(pcA + sc) : "memory");
        asm volatile("red.global.add.f32 [%0], %1;"
                     :: "l"(&g_accC[rB]), "f"(pcB + sc) : "memory");
        if (needA) {
            const int m = (rA / NN) * NF + (pA - (NN - NF));
            asm volatile("red.global.add.v2.f32 [%0], {%1, %2};"
                         :: "l"(&g_accMS[m]), "f"(pmA + sm), "f"(psA + ss) : "memory");
        }
        if (needB) {
            const int m = (rB / NN) * NF + (pB - (NN - NF));
            asm volatile("red.global.add.v2.f32 [%0], {%1, %2};"
                         :: "l"(&g_accMS[m]), "f"(pmB + sm), "f"(psB + ss) : "memory");
        }
    }
}

// ---------------------------------------------------------------------------
// Launch 4: edge MLP — 2 tiles/warp, direct-fragment gathers, all loads
// issued up front (register pipeline, depth 2).
// ---------------------------------------------------------------------------
__global__ __launch_bounds__(256) void edge_kernel(
    const float* __restrict__ x,
    const void* __restrict__ ei_raw,
    const float* __restrict__ ea)
{
    __shared__ __align__(16) float4 sE0[16], sE1[16];
    __shared__ __align__(8)  float2 sE2[16];

    const int tid  = threadIdx.x;
    const int warp = tid >> 5;
    const int lane = tid & 31;
    const int grp  = lane >> 2;
    const int tig  = lane & 3;

    if (tid < 16) {
        sE0[tid] = g_epi0[tid];
        sE1[tid] = g_epi1[tid];
        sE2[tid] = g_epi2[tid];
    }
    __syncthreads();

    const int t0 = (blockIdx.x * 8 + warp) * 2;
    if (t0 >= TILES) return;

    const unsigned qmask = 0xFu << (grp * 4);
    const float sc = g_sc, sm = g_sm, ss = g_ss;

    // ---- index loads for both tiles ----
    const int e0 = t0 * 32 + lane;
    int r0, c0, r1, c1;
    if (g_ei_is64) {
        const long long* ei = (const long long*)ei_raw;
        r0 = (int)__ldg(ei + e0);           c0 = (int)__ldg(ei + N_EDGES + e0);
        r1 = (int)__ldg(ei + e0 + 32);      c1 = (int)__ldg(ei + N_EDGES + e0 + 32);
    } else {
        const int* ei = (const int*)ei_raw;
        r0 = __ldg(ei + e0);                c0 = __ldg(ei + N_EDGES + e0);
        r1 = __ldg(ei + e0 + 32);           c1 = __ldg(ei + N_EDGES + e0 + 32);
    }
    const float av0 = __ldg(ea + e0);
    const float av1 = __ldg(ea + e0 + 32);

    // ---- shuffles: tile 0 ----
    const int rA00 = __shfl_sync(0xffffffffu, r0, grp);
    const int rB00 = __shfl_sync(0xffffffffu, r0, grp + 8);
    const int rA01 = __shfl_sync(0xffffffffu, r0, grp + 16);
    const int rB01 = __shfl_sync(0xffffffffu, r0, grp + 24);
    const int cA00 = __shfl_sync(0xffffffffu, c0, grp);
    const int cB00 = __shfl_sync(0xffffffffu, c0, grp + 8);
    const int cA01 = __shfl_sync(0xffffffffu, c0, grp + 16);
    const int cB01 = __shfl_sync(0xffffffffu, c0, grp + 24);
    // ---- shuffles: tile 1 ----
    const int rA10 = __shfl_sync(0xffffffffu, r1, grp);
    const int rB10 = __shfl_sync(0xffffffffu, r1, grp + 8);
    const int rA11 = __shfl_sync(0xffffffffu, r1, grp + 16);
    const int rB11 = __shfl_sync(0xffffffffu, r1, grp + 24);
    const int cA10 = __shfl_sync(0xffffffffu, c1, grp);
    const int cB10 = __shfl_sync(0xffffffffu, c1, grp + 8);
    const int cA11 = __shfl_sync(0xffffffffu, c1, grp + 16);
    const int cB11 = __shfl_sync(0xffffffffu, c1, grp + 24);

    // ---- all 16 fragment gathers issued back-to-back ----
    const float f000 = __ldg(x + (size_t)rA00 * 4 + tig);
    const float f001 = __ldg(x + (size_t)rB00 * 4 + tig);
    const float f002 = __ldg(x + (size_t)cA00 * 4 + tig);
    const float f003 = __ldg(x + (size_t)cB00 * 4 + tig);
    const float f010 = __ldg(x + (size_t)rA01 * 4 + tig);
    const float f011 = __ldg(x + (size_t)rB01 * 4 + tig);
    const float f012 = __ldg(x + (size_t)cA01 * 4 + tig);
    const float f013 = __ldg(x + (size_t)cB01 * 4 + tig);
    const float f100 = __ldg(x + (size_t)rA10 * 4 + tig);
    const float f101 = __ldg(x + (size_t)rB10 * 4 + tig);
    const float f102 = __ldg(x + (size_t)cA10 * 4 + tig);
    const float f103 = __ldg(x + (size_t)cB10 * 4 + tig);
    const float f110 = __ldg(x + (size_t)rA11 * 4 + tig);
    const float f111 = __ldg(x + (size_t)rB11 * 4 + tig);
    const float f112 = __ldg(x + (size_t)cA11 * 4 + tig);
    const float f113 = __ldg(x + (size_t)cB11 * 4 + tig);

    // B fragments
    unsigned B0[4], B1[4];
    #pragma unroll
    for (int nt = 0; nt < 4; nt++) {
        B0[nt] = g_W1t[tig       * HID + nt * 8 + grp];
        B1[nt] = g_W1t[(tig + 4) * HID + nt * 8 + grp];
    }

    // ea shuffles
    const float ea00 = __shfl_sync(0xffffffffu, av0, grp);
    const float ea01 = __shfl_sync(0xffffffffu, av0, grp + 8);
    const float ea02 = __shfl_sync(0xffffffffu, av0, grp + 16);
    const float ea03 = __shfl_sync(0xffffffffu, av0, grp + 24);
    const float ea10 = __shfl_sync(0xffffffffu, av1, grp);
    const float ea11 = __shfl_sync(0xffffffffu, av1, grp + 8);
    const float ea12 = __shfl_sync(0xffffffffu, av1, grp + 16);
    const float ea13 = __shfl_sync(0xffffffffu, av1, grp + 24);

    // ---- process tile 0, halves 0/1; then tile 1 ----
    process_half(f000, f001, f002, f003, ea00, ea01, rA00, rB00,
                 B0, B1, sE0, sE1, sE2, tig, qmask, sc, sm, ss);
    process_half(f010, f011, f012, f013, ea02, ea03, rA01, rB01,
                 B0, B1, sE0, sE1, sE2, tig, qmask, sc, sm, ss);
    process_half(f100, f101, f102, f103, ea10, ea11, rA10, rB10,
                 B0, B1, sE0, sE1, sE2, tig, qmask, sc, sm, ss);
    process_half(f110, f111, f112, f113, ea12, ea13, rA11, rB11,
                 B0, B1, sE0, sE1, sE2, tig, qmask, sc, sm, ss);
}

// ---------------------------------------------------------------------------
// Launch 5: per-node heads + conc sum
// ---------------------------------------------------------------------------
__global__ __launch_bounds__(256) void node_kernel(
    const float* __restrict__ x,
    const float* __restrict__ Wc,  const float* __restrict__ bc,
    const float* __restrict__ Wmu, const float* __restrict__ bmu,
    const float* __restrict__ Wsig,const float* __restrict__ bsig,
    const float* __restrict__ high,
    float* __restrict__ out)
{
    __shared__ float sWarp[8];
    const int i = blockIdx.x * blockDim.x + threadIdx.x;

    float concv = 0.0f;
    if (i < N_NODES) {
        const float  ac = g_accC[i];
        const float4 xi = __ldg(reinterpret_cast<const float4*>(x) + i);

        const float craw = xi.x * __ldg(Wc+0) + xi.y * __ldg(Wc+1)
                         + xi.z * __ldg(Wc+2) + xi.w * __ldg(Wc+3)
                         + ac + __ldg(bc) + 1e-10f;
        concv = softplusf(craw);
        g_conc[i] = concv;

        const int p = i % NN;
        if (p >= NN - NF) {
            const int m = (i / NN) * NF + (p - (NN - NF));
            const float2 ms = g_accMS[m];
            const float mraw = xi.x * __ldg(Wmu+0) + xi.y * __ldg(Wmu+1)
                             + xi.z * __ldg(Wmu+2) + xi.w * __ldg(Wmu+3)
                             + ms.x + __ldg(bmu) + 1e-20f;
            const float sraw = xi.x * __ldg(Wsig+0) + xi.y * __ldg(Wsig+1)
                             + xi.z * __ldg(Wsig+2) + xi.w * __ldg(Wsig+3)
                             + ms.y + __ldg(bsig) + 1e-20f;
            const float alpha = softplusf(mraw) + 1e-20f;
            const float beta  = softplusf(sraw) + 1e-20f;
            const int g = i / NN;
            const int j = p - (NN - NF);
            out[g * OUT_C + NN + j] = alpha / (alpha + beta) * __ldg(high + j);
        }
    }

    float s = concv;
    #pragma unroll
    for (int off = 16; off > 0; off >>= 1) s += __shfl_xor_sync(0xffffffffu, s, off);
    if ((threadIdx.x & 31) == 0) sWarp[threadIdx.x >> 5] = s;
    __syncthreads();
    if (threadIdx.x == 0) {
        float tsum = 0.f;
        #pragma unroll
        for (int w = 0; w < 8; w++) tsum += sWarp[w];
        atomicAdd(&g_S, tsum);
    }
}

// ---------------------------------------------------------------------------
// Launch 6: normalize conc
// ---------------------------------------------------------------------------
__global__ void final_kernel(float* __restrict__ out) {
    const int i = blockIdx.x * blockDim.x + threadIdx.x;
    if (i >= N_NODES) return;
    const float invS = 1.0f / (g_S + 1e-20f);
    out[(i / NN) * OUT_C + (i % NN)] = g_conc[i] * invS;
}

// ---------------------------------------------------------------------------
extern "C" void kernel_launch(void* const* d_in, const int* in_sizes, int n_in,
                              void* d_out, int out_size) {
    const float* x    = (const float*)d_in[0];
    const void*  ei   = d_in[1];
    const float* ea   = (const float*)d_in[2];
    const float* high = (const float*)d_in[3];
    const float* W1   = (const float*)d_in[4];
    const float* b1   = (const float*)d_in[5];
    const float* W2   = (const float*)d_in[6];
    const float* b2   = (const float*)d_in[7];
    const float* Wc   = (const float*)d_in[8];
    const float* bc   = (const float*)d_in[9];
    const float* Wmu  = (const float*)d_in[10];
    const float* bmu  = (const float*)d_in[11];
    const float* Wsig = (const float*)d_in[12];
    const float* bsig = (const float*)d_in[13];
    float* out = (float*)d_out;

    prep_kernel  <<<1, 32>>>((const int*)ei, W1, b1, W2, b2, Wc, Wmu, Wsig);
    zeroC_kernel <<<(N_NODES + 255) / 256, 256>>>();
    zeroMS_kernel<<<(N_TAIL + 255) / 256, 256>>>();
    edge_kernel  <<<(TILES / 2 + 7) / 8, 256>>>(x, ei, ea);   // 7813 blocks
    node_kernel  <<<(N_NODES + 255) / 256, 256>>>(x, Wc, bc, Wmu, bmu, Wsig, bsig, high, out);
    final_kernel <<<(N_NODES + 255) / 256, 256>>>(out);
}

// round 16
// speedup vs baseline: 1.0912x; 1.0912x over previous
#include <cuda_runtime.h>
#include <cstdint>

#define N_NODES 250000
#define N_EDGES 4000000
#define NODE_F  4
#define HID     32
#define NN      50
#define NF      3
#define OUT_C   53
#define TILES   (N_EDGES / 32)
#define N_TAIL  ((N_NODES / NN) * NF)   // 15000
#define NBLK    592                     // node kernel: co-resident grid

// Scratch (device globals)
__device__ float  g_accC[N_NODES];                 // 1 MB
__device__ __align__(8) float2 g_accMS[N_TAIL];    // 120 KB compact tail accumulators
__device__ float g_S;
__device__ int   g_done;
__device__ int   g_ei_is64;
__device__ float g_sc, g_sm, g_ss;                 // b2 . W*[4:36]
__device__ unsigned g_W1t[8 * HID];                // tf32 W1 rows 0..7
__device__ __align__(16) float4 g_epi0[16];        // {uc0, uc1, um0, um1} per col-pair
__device__ __align__(16) float4 g_epi1[16];        // {us0, us1, w8_0, w8_1}
__device__ __align__(8)  float2 g_epi2[16];        // {b0, b1}

__device__ __forceinline__ float softplusf(float x) {
    return fmaxf(x, 0.0f) + log1pf(expf(-fabsf(x)));
}
__device__ __forceinline__ unsigned f2tf32(float f) {
    unsigned u; asm("cvt.rna.tf32.f32 %0, %1;" : "=r"(u) : "f"(f)); return u;
}
__device__ __forceinline__ void mma_tf32(float d[4],
                                         unsigned a0, unsigned a1, unsigned a2, unsigned a3,
                                         unsigned b0, unsigned b1) {
    asm("mma.sync.aligned.m16n8k8.row.col.f32.tf32.tf32.f32 "
        "{%0,%1,%2,%3}, {%4,%5,%6,%7}, {%8,%9}, {%0,%1,%2,%3};"
        : "+f"(d[0]), "+f"(d[1]), "+f"(d[2]), "+f"(d[3])
        : "r"(a0), "r"(a1), "r"(a2), "r"(a3), "r"(b0), "r"(b1));
}

// ---------------------------------------------------------------------------
// Launch 1: fused init — block 0 does prep; all blocks zero accumulators.
// ---------------------------------------------------------------------------
__global__ void init_kernel(const int* __restrict__ ei32,
                            const float* __restrict__ W1,
                            const float* __restrict__ b1,
                            const float* __restrict__ W2,
                            const float* __restrict__ b2,
                            const float* __restrict__ Wc,
                            const float* __restrict__ Wmu,
                            const float* __restrict__ Wsig)
{
    if (blockIdx.x == 0 && threadIdx.x < 32) {
        __shared__ float suc[HID], sum_[HID], sus[HID];
        const int k = threadIdx.x;
        if (k == 0) {
            int z = 0;
            #pragma unroll
            for (int i = 1; i < 64; i += 2) z |= ei32[i];
            g_ei_is64 = (z == 0) ? 1 : 0;
            g_S = 0.0f;
            g_done = 0;
        }
        float uc = 0.f, um = 0.f, us = 0.f;
        #pragma unroll
        for (int m = 0; m < HID; m++) {
            const float w = W2[k * HID + m];
            uc = fmaf(w, Wc[NODE_F + m],   uc);
            um = fmaf(w, Wmu[NODE_F + m],  um);
            us = fmaf(w, Wsig[NODE_F + m], us);
        }
        suc[k] = uc; sum_[k] = um; sus[k] = us;

        #pragma unroll
        for (int d = 0; d < 8; d++) g_W1t[d * HID + k] = f2tf32(W1[d * HID + k]);

        __syncwarp();
        if (k < 16) {
            const int c0 = 2 * k, c1 = 2 * k + 1;
            g_epi0[k] = make_float4(suc[c0], suc[c1], sum_[c0], sum_[c1]);
            g_epi1[k] = make_float4(sus[c0], sus[c1], W1[8 * HID + c0], W1[8 * HID + c1]);
            g_epi2[k] = make_float2(b1[c0], b1[c1]);
        }

        float pc = b2[k] * Wc[NODE_F + k];
        float pm = b2[k] * Wmu[NODE_F + k];
        float ps = b2[k] * Wsig[NODE_F + k];
        #pragma unroll
        for (int off = 16; off > 0; off >>= 1) {
            pc += __shfl_xor_sync(0xffffffffu, pc, off);
            pm += __shfl_xor_sync(0xffffffffu, pm, off);
            ps += __shfl_xor_sync(0xffffffffu, ps, off);
        }
        if (k == 0) { g_sc = pc; g_sm = pm; g_ss = ps; }
    }

    if (blockIdx.x > 0) {
        const int i = (blockIdx.x - 1) * blockDim.x + threadIdx.x;
        if (i < N_NODES) g_accC[i] = 0.0f;
        if (i < N_TAIL)  g_accMS[i] = make_float2(0.f, 0.f);
    }
}

// ---------------------------------------------------------------------------
// Per-half-tile worker (R13's proven body)
// ---------------------------------------------------------------------------
__device__ __forceinline__ void process_half(
    float f0, float f1, float f2, float f3,
    float eaA, float eaB, int rA, int rB,
    const unsigned B0[4], const unsigned B1[4],
    const float4* sE0, const float4* sE1, const float2* sE2,
    int tig, unsigned qmask, float sc, float sm, float ss)
{
    const unsigned a0 = f2tf32(f0), a1 = f2tf32(f1);
    const unsigned a2 = f2tf32(f2), a3 = f2tf32(f3);
    float D[4][4];
    #pragma unroll
    for (int nt = 0; nt < 4; nt++) {
        D[nt][0] = D[nt][1] = D[nt][2] = D[nt][3] = 0.0f;
        mma_tf32(D[nt], a0, a1, a2, a3, B0[nt], B1[nt]);
    }

    const int pA = rA % NN, pB = rB % NN;
    const bool needA = (pA >= NN - NF);
    const bool needB = (pB >= NN - NF);
    const bool needMS = needA || needB;          // quad-uniform

    float pcA = 0.f, pcB = 0.f, pmA = 0.f, pmB = 0.f, psA = 0.f, psB = 0.f;
    #pragma unroll
    for (int nt = 0; nt < 4; nt++) {
        const int p = nt * 4 + tig;
        const float4 E1 = sE1[p];   // us0, us1, w8_0, w8_1
        const float2 E2 = sE2[p];   // b0, b1
        const float h0 = fmaxf(fmaf(eaA, E1.z, D[nt][0] + E2.x), 0.f);
        const float h1 = fmaxf(fmaf(eaA, E1.w, D[nt][1] + E2.y), 0.f);
        const float h2 = fmaxf(fmaf(eaB, E1.z, D[nt][2] + E2.x), 0.f);
        const float h3 = fmaxf(fmaf(eaB, E1.w, D[nt][3] + E2.y), 0.f);
        const float4 E0 = sE0[p];   // uc0, uc1, um0, um1
        pcA = fmaf(h0, E0.x, fmaf(h1, E0.y, pcA));
        pcB = fmaf(h2, E0.x, fmaf(h3, E0.y, pcB));
        if (needMS) {
            pmA = fmaf(h0, E0.z, fmaf(h1, E0.w, pmA));
            pmB = fmaf(h2, E0.z, fmaf(h3, E0.w, pmB));
            psA = fmaf(h0, E1.x, fmaf(h1, E1.y, psA));
            psB = fmaf(h2, E1.x, fmaf(h3, E1.y, psB));
        }
    }

    pcA += __shfl_xor_sync(qmask, pcA, 1); pcA += __shfl_xor_sync(qmask, pcA, 2);
    pcB += __shfl_xor_sync(qmask, pcB, 1); pcB += __shfl_xor_sync(qmask, pcB, 2);
    if (needMS) {
        pmA += __shfl_xor_sync(qmask, pmA, 1); pmA += __shfl_xor_sync(qmask, pmA, 2);
        pmB += __shfl_xor_sync(qmask, pmB, 1); pmB += __shfl_xor_sync(qmask, pmB, 2);
        psA += __shfl_xor_sync(qmask, psA, 1); psA += __shfl_xor_sync(qmask, psA, 2);
        psB += __shfl_xor_sync(qmask, psB, 1); psB += __shfl_xor_sync(qmask, psB, 2);
    }

    if (tig == 0) {
        asm volatile("red.global.add.f32 [%0], %1;"
                     :: "l"(&g_accC[rA]), "f"(pcA + sc) : "memory");
        asm volatile("red.global.add.f32 [%0], %1;"
                     :: "l"(&g_accC[rB]), "f"(pcB + sc) : "memory");
        if (needA) {
            const int m = (rA / NN) * NF + (pA - (NN - NF));
            asm volatile("red.global.add.v2.f32 [%0], {%1, %2};"
                         :: "l"(&g_accMS[m]), "f"(pmA + sm), "f"(psA + ss) : "memory");
        }
        if (needB) {
            const int m = (rB / NN) * NF + (pB - (NN - NF));
            asm volatile("red.global.add.v2.f32 [%0], {%1, %2};"
                         :: "l"(&g_accMS[m]), "f"(pmB + sm), "f"(psB + ss) : "memory");
        }
    }
}

// ---------------------------------------------------------------------------
// Launch 2: edge MLP — R13 body: 1 tile/warp, direct-fragment gathers.
// ---------------------------------------------------------------------------
__global__ __launch_bounds__(256) void edge_kernel(
    const float* __restrict__ x,
    const void* __restrict__ ei_raw,
    const float* __restrict__ ea)
{
    __shared__ __align__(16) float4 sE0[16], sE1[16];
    __shared__ __align__(8)  float2 sE2[16];

    const int tid  = threadIdx.x;
    const int warp = tid >> 5;
    const int lane = tid & 31;
    const int grp  = lane >> 2;
    const int tig  = lane & 3;

    if (tid < 16) {
        sE0[tid] = g_epi0[tid];
        sE1[tid] = g_epi1[tid];
        sE2[tid] = g_epi2[tid];
    }

    const int t = blockIdx.x * 8 + warp;
    const int e = t * 32 + lane;

    int r, c;
    if (g_ei_is64) {
        const long long* ei = (const long long*)ei_raw;
        r = (int)__ldg(ei + e);
        c = (int)__ldg(ei + N_EDGES + e);
    } else {
        const int* ei = (const int*)ei_raw;
        r = __ldg(ei + e);
        c = __ldg(ei + N_EDGES + e);
    }
    const float av = __ldg(ea + e);

    const int rA0 = __shfl_sync(0xffffffffu, r, grp);
    const int rB0 = __shfl_sync(0xffffffffu, r, grp + 8);
    const int cA0 = __shfl_sync(0xffffffffu, c, grp);
    const int cB0 = __shfl_sync(0xffffffffu, c, grp + 8);
    const int rA1 = __shfl_sync(0xffffffffu, r, grp + 16);
    const int rB1 = __shfl_sync(0xffffffffu, r, grp + 24);
    const int cA1 = __shfl_sync(0xffffffffu, c, grp + 16);
    const int cB1 = __shfl_sync(0xffffffffu, c, grp + 24);

    const float f00 = __ldg(x + (size_t)rA0 * 4 + tig);
    const float f01 = __ldg(x + (size_t)rB0 * 4 + tig);
    const float f02 = __ldg(x + (size_t)cA0 * 4 + tig);
    const float f03 = __ldg(x + (size_t)cB0 * 4 + tig);
    const float f10 = __ldg(x + (size_t)rA1 * 4 + tig);
    const float f11 = __ldg(x + (size_t)rB1 * 4 + tig);
    const float f12 = __ldg(x + (size_t)cA1 * 4 + tig);
    const float f13 = __ldg(x + (size_t)cB1 * 4 + tig);

    unsigned B0[4], B1[4];
    #pragma unroll
    for (int nt = 0; nt < 4; nt++) {
        B0[nt] = g_W1t[tig       * HID + nt * 8 + grp];
        B1[nt] = g_W1t[(tig + 4) * HID + nt * 8 + grp];
    }

    __syncthreads();

    const float eaA0 = __shfl_sync(0xffffffffu, av, grp);
    const float eaB0 = __shfl_sync(0xffffffffu, av, grp + 8);
    const float eaA1 = __shfl_sync(0xffffffffu, av, grp + 16);
    const float eaB1 = __shfl_sync(0xffffffffu, av, grp + 24);

    const unsigned qmask = 0xFu << (grp * 4);
    const float sc = g_sc, sm = g_sm, ss = g_ss;

    process_half(f00, f01, f02, f03, eaA0, eaB0, rA0, rB0,
                 B0, B1, sE0, sE1, sE2, tig, qmask, sc, sm, ss);
    process_half(f10, f11, f12, f13, eaA1, eaB1, rA1, rB1,
                 B0, B1, sE0, sE1, sE2, tig, qmask, sc, sm, ss);
}

// ---------------------------------------------------------------------------
// Launch 3: fused node heads + global sum + normalize (spin on counter).
// 592 co-resident blocks, 2 nodes/thread, conc kept in registers.
// ---------------------------------------------------------------------------
__global__ __launch_bounds__(256) void node_kernel(
    const float* __restrict__ x,
    const float* __restrict__ Wc,  const float* __restrict__ bc,
    const float* __restrict__ Wmu, const float* __restrict__ bmu,
    const float* __restrict__ Wsig,const float* __restrict__ bsig,
    const float* __restrict__ high,
    float* __restrict__ out)
{
    __shared__ float sWarp[8];
    const int base = blockIdx.x * blockDim.x + threadIdx.x;
    const int STRIDE = NBLK * 256;

    float concv[2] = {0.f, 0.f};
    int   idx[2]   = {-1, -1};

    #pragma unroll
    for (int q = 0; q < 2; q++) {
        const int i = base + q * STRIDE;
        if (i >= N_NODES) break;
        idx[q] = i;
        const float  ac = g_accC[i];
        const float4 xi = __ldg(reinterpret_cast<const float4*>(x) + i);

        const float craw = xi.x * __ldg(Wc+0) + xi.y * __ldg(Wc+1)
                         + xi.z * __ldg(Wc+2) + xi.w * __ldg(Wc+3)
                         + ac + __ldg(bc) + 1e-10f;
        concv[q] = softplusf(craw);

        const int p = i % NN;
        if (p >= NN - NF) {
            const int m = (i / NN) * NF + (p - (NN - NF));
            const float2 ms = g_accMS[m];
            const float mraw = xi.x * __ldg(Wmu+0) + xi.y * __ldg(Wmu+1)
                             + xi.z * __ldg(Wmu+2) + xi.w * __ldg(Wmu+3)
                             + ms.x + __ldg(bmu) + 1e-20f;
            const float sraw = xi.x * __ldg(Wsig+0) + xi.y * __ldg(Wsig+1)
                             + xi.z * __ldg(Wsig+2) + xi.w * __ldg(Wsig+3)
                             + ms.y + __ldg(bsig) + 1e-20f;
            const float alpha = softplusf(mraw) + 1e-20f;
            const float beta  = softplusf(sraw) + 1e-20f;
            const int g = i / NN;
            const int j = p - (NN - NF);
            out[g * OUT_C + NN + j] = alpha / (alpha + beta) * __ldg(high + j);
        }
    }

    // block reduction of conc into g_S
    float s = concv[0] + concv[1];
    #pragma unroll
    for (int off = 16; off > 0; off >>= 1) s += __shfl_xor_sync(0xffffffffu, s, off);
    if ((threadIdx.x & 31) == 0) sWarp[threadIdx.x >> 5] = s;
    __syncthreads();
    if (threadIdx.x == 0) {
        float tsum = 0.f;
        #pragma unroll
        for (int w = 0; w < 8; w++) tsum += sWarp[w];
        atomicAdd(&g_S, tsum);
        __threadfence();
        atomicAdd(&g_done, 1);
    }

    // spin until all blocks contributed (grid is co-resident by construction)
    if (threadIdx.x == 0) {
        int d;
        do {
            asm volatile("ld.acquire.gpu.b32 %0, [%1];"
                         : "=r"(d) : "l"(&g_done) : "memory");
        } while (d < NBLK);
    }
    __syncthreads();

    const float invS = 1.0f / (g_S + 1e-20f);
    #pragma unroll
    for (int q = 0; q < 2; q++) {
        if (idx[q] >= 0)
            out[(idx[q] / NN) * OUT_C + (idx[q] % NN)] = concv[q] * invS;
    }
}

// ---------------------------------------------------------------------------
extern "C" void kernel_launch(void* const* d_in, const int* in_sizes, int n_in,
                              void* d_out, int out_size) {
    const float* x    = (const float*)d_in[0];
    const void*  ei   = d_in[1];
    const float* ea   = (const float*)d_in[2];
    const float* high = (const float*)d_in[3];
    const float* W1   = (const float*)d_in[4];
    const float* b1   = (const float*)d_in[5];
    const float* W2   = (const float*)d_in[6];
    const float* b2   = (const float*)d_in[7];
    const float* Wc   = (const float*)d_in[8];
    const float* bc   = (const float*)d_in[9];
    const float* Wmu  = (const float*)d_in[10];
    const float* bmu  = (const float*)d_in[11];
    const float* Wsig = (const float*)d_in[12];
    const float* bsig = (const float*)d_in[13];
    float* out = (float*)d_out;

    init_kernel<<<(N_NODES + 255) / 256 + 1, 256>>>(
        (const int*)ei, W1, b1, W2, b2, Wc, Wmu, Wsig);
    edge_kernel<<<TILES / 8, 256>>>(x, ei, ea);   // 15625 blocks
    node_kernel<<<NBLK, 256>>>(x, Wc, bc, Wmu, bmu, Wsig, bsig, high, out);
}

// round 17
// speedup vs baseline: 1.1914x; 1.0918x over previous
#include <cuda_runtime.h>
#include <cstdint>

#define N_NODES 250000
#define N_EDGES 4000000
#define NODE_F  4
#define HID     32
#define NN      50
#define NF      3
#define OUT_C   53
#define ROWW    12    // staging row stride in words (48 B)
#define TILES   (N_EDGES / 32)

// Scratch (device globals; zero-initialized at module load, and node_kernel
// re-zeroes after reading so every call sees clean accumulators)
__device__ float  g_accC[N_NODES];                 // 1 MB
__device__ __align__(8) float2 g_accMS[N_NODES];   // 2 MB (tail nodes only)
__device__ float g_conc[N_NODES];
__device__ float g_S;
__device__ int   g_ei_is64;
__device__ float g_sc, g_sm, g_ss;                 // b2 . W*[4:36]
__device__ unsigned g_W1t[8 * HID];                // tf32 W1 rows 0..7
__device__ __align__(16) float4 g_epi0[16];        // {uc0, uc1, um0, um1} per col-pair
__device__ __align__(16) float4 g_epi1[16];        // {us0, us1, w8_0, w8_1}
__device__ __align__(8)  float2 g_epi2[16];        // {b0, b1}

__device__ __forceinline__ float softplusf(float x) {
    return fmaxf(x, 0.0f) + log1pf(expf(-fabsf(x)));
}
__device__ __forceinline__ unsigned f2tf32(float f) {
    unsigned u; asm("cvt.rna.tf32.f32 %0, %1;" : "=r"(u) : "f"(f)); return u;
}
__device__ __forceinline__ void mma_tf32(float d[4],
                                         unsigned a0, unsigned a1, unsigned a2, unsigned a3,
                                         unsigned b0, unsigned b1) {
    asm("mma.sync.aligned.m16n8k8.row.col.f32.tf32.tf32.f32 "
        "{%0,%1,%2,%3}, {%4,%5,%6,%7}, {%8,%9}, {%0,%1,%2,%3};"
        : "+f"(d[0]), "+f"(d[1]), "+f"(d[2]), "+f"(d[3])
        : "r"(a0), "r"(a1), "r"(a2), "r"(a3), "r"(b0), "r"(b1));
}
__device__ __forceinline__ void cp_async16(unsigned dst, const void* src) {
    asm volatile("cp.async.ca.shared.global [%0], [%1], 16;" :: "r"(dst), "l"(src));
}

// ---------------------------------------------------------------------------
// Launch 1: prep (1 warp — kept standalone; fusing it into a wide grid puts
// its serial chain on that kernel's critical path, R16 lesson)
// ---------------------------------------------------------------------------
__global__ void prep_kernel(const int* __restrict__ ei32,
                            const float* __restrict__ W1,
                            const float* __restrict__ b1,
                            const float* __restrict__ W2,
                            const float* __restrict__ b2,
                            const float* __restrict__ Wc,
                            const float* __restrict__ Wmu,
                            const float* __restrict__ Wsig)
{
    __shared__ float suc[HID], sum_[HID], sus[HID];
    const int k = threadIdx.x;
    if (k == 0) {
        int z = 0;
        #pragma unroll
        for (int i = 1; i < 64; i += 2) z |= ei32[i];
        g_ei_is64 = (z == 0) ? 1 : 0;
        g_S = 0.0f;
    }
    float uc = 0.f, um = 0.f, us = 0.f;
    #pragma unroll
    for (int m = 0; m < HID; m++) {
        const float w = W2[k * HID + m];
        uc = fmaf(w, Wc[NODE_F + m],   uc);
        um = fmaf(w, Wmu[NODE_F + m],  um);
        us = fmaf(w, Wsig[NODE_F + m], us);
    }
    suc[k] = uc; sum_[k] = um; sus[k] = us;

    #pragma unroll
    for (int d = 0; d < 8; d++) g_W1t[d * HID + k] = f2tf32(W1[d * HID + k]);

    __syncwarp();
    if (k < 16) {
        const int c0 = 2 * k, c1 = 2 * k + 1;
        g_epi0[k] = make_float4(suc[c0], suc[c1], sum_[c0], sum_[c1]);
        g_epi1[k] = make_float4(sus[c0], sus[c1], W1[8 * HID + c0], W1[8 * HID + c1]);
        g_epi2[k] = make_float2(b1[c0], b1[c1]);
    }

    float pc = b2[k] * Wc[NODE_F + k];
    float pm = b2[k] * Wmu[NODE_F + k];
    float ps = b2[k] * Wsig[NODE_F + k];
    #pragma unroll
    for (int off = 16; off > 0; off >>= 1) {
        pc += __shfl_xor_sync(0xffffffffu, pc, off);
        pm += __shfl_xor_sync(0xffffffffu, pm, off);
        ps += __shfl_xor_sync(0xffffffffu, ps, off);
    }
    if (k == 0) { g_sc = pc; g_sm = pm; g_ss = ps; }
}

// ---------------------------------------------------------------------------
// Per-tile worker (R12's proven body)
// ---------------------------------------------------------------------------
__device__ __forceinline__ void process_tile(
    const float* aw, int r, float av,
    const unsigned B0[4], const unsigned B1[4],
    const float4* sE0, const float4* sE1, const float2* sE2,
    int lane, int grp, int tig, float sc, float sm, float ss)
{
    float D[2][4][4];
    #pragma unroll
    for (int h = 0; h < 2; h++) {
        const unsigned a0 = f2tf32(aw[(h * 16 + grp)     * ROWW + tig]);
        const unsigned a1 = f2tf32(aw[(h * 16 + grp + 8) * ROWW + tig]);
        const unsigned a2 = f2tf32(aw[(h * 16 + grp)     * ROWW + tig + 4]);
        const unsigned a3 = f2tf32(aw[(h * 16 + grp + 8) * ROWW + tig + 4]);
        #pragma unroll
        for (int nt = 0; nt < 4; nt++) {
            D[h][nt][0] = D[h][nt][1] = D[h][nt][2] = D[h][nt][3] = 0.0f;
            mma_tf32(D[h][nt], a0, a1, a2, a3, B0[nt], B1[nt]);
        }
    }

    const float eaA0 = __shfl_sync(0xffffffffu, av, grp);
    const float eaB0 = __shfl_sync(0xffffffffu, av, grp + 8);
    const float eaA1 = __shfl_sync(0xffffffffu, av, grp + 16);
    const float eaB1 = __shfl_sync(0xffffffffu, av, grp + 24);

    float pcA[2] = {0.f, 0.f}, pcB[2] = {0.f, 0.f};
    float pmA[2] = {0.f, 0.f}, pmB[2] = {0.f, 0.f};
    float psA[2] = {0.f, 0.f}, psB[2] = {0.f, 0.f};

    #pragma unroll
    for (int nt = 0; nt < 4; nt++) {
        const int p = nt * 4 + tig;
        const float4 E0 = sE0[p];
        const float4 E1 = sE1[p];
        const float2 E2 = sE2[p];
        #pragma unroll
        for (int h = 0; h < 2; h++) {
            const float eaA = h ? eaA1 : eaA0;
            const float eaB = h ? eaB1 : eaB0;
            const float h0 = fmaxf(fmaf(eaA, E1.z, D[h][nt][0] + E2.x), 0.f);
            const float h1 = fmaxf(fmaf(eaA, E1.w, D[h][nt][1] + E2.y), 0.f);
            const float h2 = fmaxf(fmaf(eaB, E1.z, D[h][nt][2] + E2.x), 0.f);
            const float h3 = fmaxf(fmaf(eaB, E1.w, D[h][nt][3] + E2.y), 0.f);
            pcA[h] = fmaf(h0, E0.x, fmaf(h1, E0.y, pcA[h]));
            pcB[h] = fmaf(h2, E0.x, fmaf(h3, E0.y, pcB[h]));
            pmA[h] = fmaf(h0, E0.z, fmaf(h1, E0.w, pmA[h]));
            pmB[h] = fmaf(h2, E0.z, fmaf(h3, E0.w, pmB[h]));
            psA[h] = fmaf(h0, E1.x, fmaf(h1, E1.y, psA[h]));
            psB[h] = fmaf(h2, E1.x, fmaf(h3, E1.y, psB[h]));
        }
    }

    #pragma unroll
    for (int h = 0; h < 2; h++) {
        #pragma unroll
        for (int off = 1; off <= 2; off <<= 1) {
            pcA[h] += __shfl_xor_sync(0xffffffffu, pcA[h], off);
            pcB[h] += __shfl_xor_sync(0xffffffffu, pcB[h], off);
            pmA[h] += __shfl_xor_sync(0xffffffffu, pmA[h], off);
            pmB[h] += __shfl_xor_sync(0xffffffffu, pmB[h], off);
            psA[h] += __shfl_xor_sync(0xffffffffu, psA[h], off);
            psB[h] += __shfl_xor_sync(0xffffffffu, psB[h], off);
        }
        const int rA = __shfl_sync(0xffffffffu, r, h * 16 + grp);
        const int rB = __shfl_sync(0xffffffffu, r, h * 16 + grp + 8);
        if (tig == 0) {
            asm volatile("red.global.add.f32 [%0], %1;"
                         :: "l"(&g_accC[rA]), "f"(pcA[h] + sc) : "memory");
            asm volatile("red.global.add.f32 [%0], %1;"
                         :: "l"(&g_accC[rB]), "f"(pcB[h] + sc) : "memory");
            if (rA % NN >= NN - NF)
                asm volatile("red.global.add.v2.f32 [%0], {%1, %2};"
                             :: "l"(&g_accMS[rA]), "f"(pmA[h] + sm), "f"(psA[h] + ss) : "memory");
            if (rB % NN >= NN - NF)
                asm volatile("red.global.add.v2.f32 [%0], {%1, %2};"
                             :: "l"(&g_accMS[rB]), "f"(pmB[h] + sm), "f"(psB[h] + ss) : "memory");
        }
    }
}

// ---------------------------------------------------------------------------
// Launch 2: edge MLP — R12 verbatim: 2 tiles/warp, cp.async pipelined
// ---------------------------------------------------------------------------
__global__ __launch_bounds__(256) void edge_kernel(
    const float* __restrict__ x,
    const void* __restrict__ ei_raw,
    const float* __restrict__ ea)
{
    __shared__ __align__(16) float sA[2 * 8 * 32 * ROWW];  // 24 KB staging
    __shared__ __align__(16) float4 sE0[16], sE1[16];
    __shared__ __align__(8)  float2 sE2[16];

    const int tid  = threadIdx.x;
    const int warp = tid >> 5;
    const int lane = tid & 31;
    const int grp  = lane >> 2;
    const int tig  = lane & 3;

    if (tid < 16) {
        sE0[tid] = g_epi0[tid];
        sE1[tid] = g_epi1[tid];
        sE2[tid] = g_epi2[tid];
    }

    const int t0 = (blockIdx.x * 8 + warp) * 2;
    if (t0 >= TILES) { __syncthreads(); return; }

    const int is64 = g_ei_is64;
    float* aw0 = &sA[(warp * 2 + 0) * 32 * ROWW];
    float* aw1 = &sA[(warp * 2 + 1) * 32 * ROWW];

    int r0, c0, r1, c1;
    {
        const int e0 = t0 * 32 + lane;
        const int e1 = e0 + 32;
        if (is64) {
            const long long* ei = (const long long*)ei_raw;
            r0 = (int)__ldg(ei + e0); c0 = (int)__ldg(ei + N_EDGES + e0);
            r1 = (int)__ldg(ei + e1); c1 = (int)__ldg(ei + N_EDGES + e1);
        } else {
            const int* ei = (const int*)ei_raw;
            r0 = __ldg(ei + e0); c0 = __ldg(ei + N_EDGES + e0);
            r1 = __ldg(ei + e1); c1 = __ldg(ei + N_EDGES + e1);
        }
    }
    const float av0 = __ldg(ea + t0 * 32 + lane);
    const float av1 = __ldg(ea + t0 * 32 + 32 + lane);

    const unsigned a0addr = (unsigned)__cvta_generic_to_shared(&aw0[lane * ROWW]);
    cp_async16(a0addr,      x + (size_t)r0 * 4);
    cp_async16(a0addr + 16, x + (size_t)c0 * 4);
    asm volatile("cp.async.commit_group;");
    const unsigned a1addr = (unsigned)__cvta_generic_to_shared(&aw1[lane * ROWW]);
    cp_async16(a1addr,      x + (size_t)r1 * 4);
    cp_async16(a1addr + 16, x + (size_t)c1 * 4);
    asm volatile("cp.async.commit_group;");

    unsigned B0[4], B1[4];
    #pragma unroll
    for (int nt = 0; nt < 4; nt++) {
        B0[nt] = g_W1t[tig       * HID + nt * 8 + grp];
        B1[nt] = g_W1t[(tig + 4) * HID + nt * 8 + grp];
    }

    const float sc = g_sc, sm = g_sm, ss = g_ss;

    __syncthreads();   // sE visibility; gathers still in flight

    asm volatile("cp.async.wait_group 1;");
    __syncwarp();
    process_tile(aw0, r0, av0, B0, B1, sE0, sE1, sE2, lane, grp, tig, sc, sm, ss);

    asm volatile("cp.async.wait_group 0;");
    __syncwarp();
    process_tile(aw1, r1, av1, B0, B1, sE0, sE1, sE2, lane, grp, tig, sc, sm, ss);
}

// ---------------------------------------------------------------------------
// Launch 3: per-node heads + conc sum; re-zeroes accumulators for next call
// ---------------------------------------------------------------------------
__global__ __launch_bounds__(256) void node_kernel(
    const float* __restrict__ x,
    const float* __restrict__ Wc,  const float* __restrict__ bc,
    const float* __restrict__ Wmu, const float* __restrict__ bmu,
    const float* __restrict__ Wsig,const float* __restrict__ bsig,
    const float* __restrict__ high,
    float* __restrict__ out)
{
    __shared__ float sWarp[8];
    const int i = blockIdx.x * blockDim.x + threadIdx.x;

    float concv = 0.0f;
    if (i < N_NODES) {
        const float  ac = g_accC[i];
        g_accC[i] = 0.0f;                       // clean for next call
        const float4 xi = __ldg(reinterpret_cast<const float4*>(x) + i);

        const float craw = xi.x * __ldg(Wc+0) + xi.y * __ldg(Wc+1)
                         + xi.z * __ldg(Wc+2) + xi.w * __ldg(Wc+3)
                         + ac + __ldg(bc) + 1e-10f;
        concv = softplusf(craw);
        g_conc[i] = concv;

        const int p = i % NN;
        if (p >= NN - NF) {
            const float2 ms = g_accMS[i];
            g_accMS[i] = make_float2(0.f, 0.f); // clean for next call
            const float mraw = xi.x * __ldg(Wmu+0) + xi.y * __ldg(Wmu+1)
                             + xi.z * __ldg(Wmu+2) + xi.w * __ldg(Wmu+3)
                             + ms.x + __ldg(bmu) + 1e-20f;
            const float sraw = xi.x * __ldg(Wsig+0) + xi.y * __ldg(Wsig+1)
                             + xi.z * __ldg(Wsig+2) + xi.w * __ldg(Wsig+3)
                             + ms.y + __ldg(bsig) + 1e-20f;
            const float alpha = softplusf(mraw) + 1e-20f;
            const float beta  = softplusf(sraw) + 1e-20f;
            const int g = i / NN;
            const int j = p - (NN - NF);
            out[g * OUT_C + NN + j] = alpha / (alpha + beta) * __ldg(high + j);
        }
    }

    float s = concv;
    #pragma unroll
    for (int off = 16; off > 0; off >>= 1) s += __shfl_xor_sync(0xffffffffu, s, off);
    if ((threadIdx.x & 31) == 0) sWarp[threadIdx.x >> 5] = s;
    __syncthreads();
    if (threadIdx.x == 0) {
        float tsum = 0.f;
        #pragma unroll
        for (int w = 0; w < 8; w++) tsum += sWarp[w];
        atomicAdd(&g_S, tsum);
    }
}

// ---------------------------------------------------------------------------
// Launch 4: normalize conc
// ---------------------------------------------------------------------------
__global__ void final_kernel(float* __restrict__ out) {
    const int i = blockIdx.x * blockDim.x + threadIdx.x;
    if (i >= N_NODES) return;
    const float invS = 1.0f / (g_S + 1e-20f);
    out[(i / NN) * OUT_C + (i % NN)] = g_conc[i] * invS;
}

// ---------------------------------------------------------------------------
extern "C" void kernel_launch(void* const* d_in, const int* in_sizes, int n_in,
                              void* d_out, int out_size) {
    const float* x    = (const float*)d_in[0];
    const void*  ei   = d_in[1];
    const float* ea   = (const float*)d_in[2];
    const float* high = (const float*)d_in[3];
    const float* W1   = (const float*)d_in[4];
    const float* b1   = (const float*)d_in[5];
    const float* W2   = (const float*)d_in[6];
    const float* b2   = (const float*)d_in[7];
    const float* Wc   = (const float*)d_in[8];
    const float* bc   = (const float*)d_in[9];
    const float* Wmu  = (const float*)d_in[10];
    const float* bmu  = (const float*)d_in[11];
    const float* Wsig = (const float*)d_in[12];
    const float* bsig = (const float*)d_in[13];
    float* out = (float*)d_out;

    prep_kernel <<<1, 32>>>((const int*)ei, W1, b1, W2, b2, Wc, Wmu, Wsig);
    edge_kernel <<<(TILES / 2 + 7) / 8, 256>>>(x, ei, ea);   // 7813 blocks
    node_kernel <<<(N_NODES + 255) / 256, 256>>>(x, Wc, bc, Wmu, bmu, Wsig, bsig, high, out);
    final_kernel<<<(N_NODES + 255) / 256, 256>>>(out);
}